// round 8
// baseline (speedup 1.0000x reference)
#include <cuda_runtime.h>
#include <cuda_bf16.h>
#include <math.h>
#include <stdint.h>

#define B_ 64
#define S_ 512
#define I_ 256
#define H_ 1024
#define O_ 128

// ---------------- static device scratch (no dynamic allocation) ------------
__device__ __nv_bfloat16 g_buf[((size_t)B_ * S_ + 32) * H_]; // g2=(1-a)(1-b)(ff+bias), bf16 (+32 rows prefetch pad)
__device__ __nv_bfloat16 wbf[(size_t)H_ * I_];               // W_in in bf16
__device__ unsigned      spk_buf[(size_t)B_ * S_ * (H_ / 32)];
__device__ unsigned char rowflag[(size_t)B_ * S_];
__device__ float         s1_buf[H_];                          // (1-alpha)(1-beta)
__device__ float         s2_buf[H_];                          // b_in + b_rec
__device__ unsigned      chunk_sync[B_ * 8];                  // per (batch,chunk) cross-CTA combine
__device__ unsigned      step_sync[B_ * S_];                  // per (batch,step) combine (replay path)

__device__ __forceinline__ float sigmoidf_(float x) { return 1.f / (1.f + expf(-x)); }

__device__ __forceinline__ uint32_t smem_u32(const void* p) {
    uint32_t a;
    asm("{ .reg .u64 t; cvta.to.shared.u64 t, %1; cvt.u32.u64 %0, t; }" : "=r"(a) : "l"(p));
    return a;
}
__device__ __forceinline__ void cp_async16(uint32_t dst, const void* src) {
    asm volatile("cp.async.cg.shared.global [%0], [%1], 16;" :: "r"(dst), "l"(src) : "memory");
}
__device__ __forceinline__ void cp_commit() {
    asm volatile("cp.async.commit_group;" ::: "memory");
}

// ---------------------------------------------------------------------------
// Phase 0: W_in -> bf16; per-neuron constants; zero sync flags (every launch,
// so graph replays are deterministic).
// ---------------------------------------------------------------------------
__global__ void prep_kernel(const float* __restrict__ W_in, const float* __restrict__ b_in,
                            const float* __restrict__ b_rec, const float* __restrict__ tau_m,
                            const float* __restrict__ tau_n) {
    int idx = blockIdx.x * 1024 + threadIdx.x;   // 256 blocks cover 262144 = H*I
    wbf[idx] = __float2bfloat16(W_in[idx]);
    if (idx < B_ * S_) step_sync[idx] = 0;
    if (idx < B_ * 8)  chunk_sync[idx] = 0;
    if (blockIdx.x == 0) {
        int h = threadIdx.x;
        float a1 = 1.f - sigmoidf_(tau_m[h]);
        float b1 = 1.f - sigmoidf_(tau_n[h]);
        s1_buf[h] = a1 * b1;
        s2_buf[h] = b_in[h] + b_rec[h];
    }
}

// ---------------------------------------------------------------------------
// Phase 1: HMMA GEMM, fp32 A converted on the fly.
// g[m][n] = s1[n]*(X[m,:]·W[n,:] + s2[n]), bf16 out.
// C[32768,1024] = X[32768,256](fp32) @ Wbf[1024,256]^T(bf16).
// BM=128, BN=256, BK=32, 512 threads (16 warps, warp tile 32x64),
// 3-stage cp.async pipeline. A smem fp32 (row 160B), B smem bf16 (row 80B,
// conflict-free for the fragment pattern).
// ---------------------------------------------------------------------------
#define BK 32
#define ASTG 20480                      // 128 rows * 160B
#define BSTG 20480                      // 256 rows * 80B
#define SM_B   (3 * ASTG)               // 61440
#define SM_S12 (SM_B + 3 * BSTG)        // 122880
#define SMEM_BYTES (SM_S12 + 256 * 8)   // 124928

__global__ __launch_bounds__(512, 1)
void ff_gemm_kernel(const float* __restrict__ X) {
    extern __shared__ char smem[];
    uint32_t sa  = smem_u32(smem);
    uint32_t sbm = sa + SM_B;
    float2* s12 = (float2*)(smem + SM_S12);

    int tid = threadIdx.x, lane = tid & 31, warp = tid >> 5;
    int nt = blockIdx.x & 3, mg = blockIdx.x >> 2;
    int m0 = mg * 128, n0 = nt * 256;

    if (tid < 256) s12[tid] = make_float2(s1_buf[n0 + tid], s2_buf[n0 + tid]);

    // loader slots: A = 1024 16B-chunks (128 rows x 8), B = 1024 (256 rows x 4)
    int ia0 = tid * 2, ia1 = tid * 2 + 1;
    int ar0 = ia0 >> 3, ac0 = ia0 & 7, ar1 = ia1 >> 3, ac1 = ia1 & 7;
    int br0 = ia0 >> 2, bc0 = ia0 & 3, br1 = ia1 >> 2, bc1 = ia1 & 3;
    const float* Ab = X + (size_t)m0 * I_;
    const __nv_bfloat16* Bb = wbf + (size_t)n0 * I_;

#define ISSUE(kt) do { int st = (kt) % 3; int k0 = (kt) * BK;                    \
        cp_async16(sa + st * ASTG + ar0 * 160 + ac0 * 16,                        \
                   Ab + (size_t)ar0 * I_ + k0 + ac0 * 4);                        \
        cp_async16(sa + st * ASTG + ar1 * 160 + ac1 * 16,                        \
                   Ab + (size_t)ar1 * I_ + k0 + ac1 * 4);                        \
        cp_async16(sbm + st * BSTG + br0 * 80 + bc0 * 16,                        \
                   Bb + (size_t)br0 * I_ + k0 + bc0 * 8);                        \
        cp_async16(sbm + st * BSTG + br1 * 80 + bc1 * 16,                        \
                   Bb + (size_t)br1 * I_ + k0 + bc1 * 8);                        \
        cp_commit(); } while (0)

    ISSUE(0);
    ISSUE(1);

    int wm = (warp >> 2) * 32;    // 4 warp rows x 32
    int wn = (warp & 3) * 64;     // 4 warp cols x 64
    int fr = lane >> 2, fc = (lane & 3) * 2;

    float acc[2][8][4];
#pragma unroll
    for (int i = 0; i < 2; i++)
#pragma unroll
        for (int j = 0; j < 8; j++)
#pragma unroll
            for (int r = 0; r < 4; r++) acc[i][j][r] = 0.f;

    for (int kt = 0; kt < 8; kt++) {
        if (kt < 7) asm volatile("cp.async.wait_group 1;" ::: "memory");
        else        asm volatile("cp.async.wait_group 0;" ::: "memory");
        __syncthreads();
        if (kt + 2 < 8) ISSUE(kt + 2);

        const char* As = smem + (kt % 3) * ASTG;
        const char* Bs = smem + SM_B + (kt % 3) * BSTG;
#pragma unroll
        for (int ks = 0; ks < 2; ks++) {
            unsigned afr[2][4], bfr[8][2];
#pragma unroll
            for (int mi = 0; mi < 2; mi++) {
                int rb = wm + mi * 16;
                const float* p0 = (const float*)(As + (rb + fr) * 160) + ks * 16 + fc;
                const float* p1 = (const float*)(As + (rb + fr + 8) * 160) + ks * 16 + fc;
                float2 v0 = *(const float2*)p0;
                float2 v1 = *(const float2*)p1;
                float2 v2 = *(const float2*)(p0 + 8);
                float2 v3 = *(const float2*)(p1 + 8);
                __nv_bfloat162 t0 = __floats2bfloat162_rn(v0.x, v0.y); afr[mi][0] = *(unsigned*)&t0;
                __nv_bfloat162 t1 = __floats2bfloat162_rn(v1.x, v1.y); afr[mi][1] = *(unsigned*)&t1;
                __nv_bfloat162 t2 = __floats2bfloat162_rn(v2.x, v2.y); afr[mi][2] = *(unsigned*)&t2;
                __nv_bfloat162 t3 = __floats2bfloat162_rn(v3.x, v3.y); afr[mi][3] = *(unsigned*)&t3;
            }
#pragma unroll
            for (int ni = 0; ni < 8; ni++) {
                int cb = wn + ni * 8 + fr;
                const char* base = Bs + cb * 80 + (ks * 16 + fc) * 2;
                bfr[ni][0] = *(const unsigned*)base;
                bfr[ni][1] = *(const unsigned*)(base + 16);
            }
#pragma unroll
            for (int mi = 0; mi < 2; mi++)
#pragma unroll
                for (int ni = 0; ni < 8; ni++) {
                    asm volatile(
                        "mma.sync.aligned.m16n8k16.row.col.f32.bf16.bf16.f32 "
                        "{%0,%1,%2,%3}, {%4,%5,%6,%7}, {%8,%9}, {%0,%1,%2,%3};"
                        : "+f"(acc[mi][ni][0]), "+f"(acc[mi][ni][1]),
                          "+f"(acc[mi][ni][2]), "+f"(acc[mi][ni][3])
                        : "r"(afr[mi][0]), "r"(afr[mi][1]), "r"(afr[mi][2]), "r"(afr[mi][3]),
                          "r"(bfr[ni][0]), "r"(bfr[ni][1]));
                }
        }
    }

    // Epilogue: g = s1*(c + s2), bf16
#pragma unroll
    for (int mi = 0; mi < 2; mi++) {
#pragma unroll
        for (int ni = 0; ni < 8; ni++) {
            int nloc = wn + ni * 8 + fc;
            int n = n0 + nloc;
            float2 pa = s12[nloc], pb = s12[nloc + 1];
            int ma = m0 + wm + mi * 16 + fr;
            *(__nv_bfloat162*)&g_buf[(size_t)ma * H_ + n] =
                __floats2bfloat162_rn(pa.x * (acc[mi][ni][0] + pa.y), pb.x * (acc[mi][ni][1] + pb.y));
            *(__nv_bfloat162*)&g_buf[(size_t)(ma + 8) * H_ + n] =
                __floats2bfloat162_rn(pa.x * (acc[mi][ni][2] + pa.y), pb.x * (acc[mi][ni][3] + pb.y));
        }
    }
#undef ISSUE
}

// ---------------------------------------------------------------------------
// Phase 2: speculative chunked scan, 2 CTAs per batch (512 neurons each).
// D = beta*D + g2 (+ s1c*rec); mem = alpha*mem + D; spike iff mem>1.
// 64-step optimistic chunks; ONE block-barrier + ONE cross-CTA flag exchange
// per chunk. Exact per-step replay (ballot + sparse W_rec gather + per-step
// cross-CTA sync) on any detected crossing.
// ---------------------------------------------------------------------------
__global__ __launch_bounds__(512, 1)
void scan_kernel(const float* __restrict__ tau_m, const float* __restrict__ tau_n,
                 const float* __restrict__ W_rec) {
    __shared__ int s_any;
    int bc = blockIdx.x;          // 0..127
    int b = bc >> 1, hb = bc & 1;
    int tid = threadIdx.x;
    int h = hb * 512 + tid;

    float alpha = sigmoidf_(tau_m[h]);
    float beta  = sigmoidf_(tau_n[h]);
    float s1c = (1.f - alpha) * (1.f - beta);
    const __nv_bfloat16* gp = g_buf + (size_t)b * S_ * H_ + h;
    unsigned* spkrow = spk_buf + (size_t)b * S_ * 32;
    unsigned char* rf = rowflag + (size_t)b * S_;
    const float* wr = W_rec + (size_t)h * H_;

    float mem = 0.f, D = 0.f;
    __nv_bfloat16 ring[32];
#pragma unroll
    for (int i = 0; i < 32; i++) ring[i] = gp[(size_t)i * H_];
    const __nv_bfloat16* pf = gp + (size_t)32 * H_;   // g_buf has +32 rows pad

    int carry = 0;
    for (int chunk = 0; chunk < 8; chunk++) {
        int base = chunk * 64;
        float mem0 = mem, D0 = D, maxm = 0.f;
        for (int u = 0; u < 2; u++) {
#pragma unroll
            for (int v = 0; v < 32; v++) {
                float gv = __bfloat162float(ring[v]);
                ring[v] = *pf; pf += H_;
                D = fmaf(beta, D, gv);
                mem = fmaf(alpha, mem, D);
                maxm = fmaxf(maxm, mem);
            }
        }
        int lany = __syncthreads_or(maxm > 1.f);
        if (tid == 0) {
            __threadfence();
            atomicAdd(&chunk_sync[b * 8 + chunk], 0x10000u | (unsigned)lany);
            unsigned v;
            do { v = *((volatile unsigned*)&chunk_sync[b * 8 + chunk]); } while ((v >> 16) < 2u);
            __threadfence();
            s_any = (int)(v & 0xFFFFu);
        }
        __syncthreads();
        int any = s_any;
        __syncthreads();

        if (!(any | carry)) {
            if (hb == 0 && tid < 64) rf[base + tid] = 0;
            carry = 0;
        } else {
            // exact replay of this chunk (cold path)
            mem = mem0; D = D0;
            int prev = carry;
            for (int tt = 0; tt < 64; tt++) {
                int t = base + tt;
                float rec = 0.f;
                if (prev) {
                    const unsigned* mrow = spkrow + (size_t)(t - 1) * 32;
                    for (int w2 = 0; w2 < 32; w2++) {
                        unsigned msk = mrow[w2];
                        while (msk) {
                            int j = __ffs((int)msk) - 1;
                            rec += wr[w2 * 32 + j];
                            msk &= msk - 1;
                        }
                    }
                }
                float gv = __bfloat162float(gp[(size_t)t * H_]);
                D = fmaf(beta, D, fmaf(s1c, rec, gv));
                mem = fmaf(alpha, mem, D);
                int spike = mem > 1.f;
                if (spike) mem = 0.f;
                unsigned bal = __ballot_sync(0xffffffffu, spike);
                if ((tid & 31) == 0) spkrow[(size_t)t * 32 + hb * 16 + (tid >> 5)] = bal;
                int lor = __syncthreads_or(spike);
                if (tid == 0) {
                    __threadfence();
                    atomicAdd(&step_sync[b * S_ + t], 0x10000u | (unsigned)lor);
                    unsigned v;
                    do { v = *((volatile unsigned*)&step_sync[b * S_ + t]); } while ((v >> 16) < 2u);
                    __threadfence();
                    s_any = (int)(v & 0xFFFFu);
                }
                __syncthreads();
                prev = s_any ? 1 : 0;
                __syncthreads();
                if (tid == 0 && hb == 0) rf[t] = (unsigned char)prev;
            }
            carry = prev;
        }
    }
}

// ---------------------------------------------------------------------------
// Phase 3: out[b,t,:] = sigmoid(spike @ W_out^T + b_out). One warp per row.
// rowflag==0 fast path: broadcast precomputed sigmoid(b_out), no mask reads.
// ---------------------------------------------------------------------------
__global__ __launch_bounds__(256)
void out_kernel(const float* __restrict__ W_out, const float* __restrict__ b_out,
                float* __restrict__ out) {
    __shared__ float sig[O_];
    int tid = threadIdx.x;
    if (tid < O_) sig[tid] = sigmoidf_(b_out[tid]);
    __syncthreads();

    int warp = tid >> 5, lane = tid & 31;
    int row = blockIdx.x * 8 + warp;
    float* orow = out + (size_t)row * O_;
    if (!rowflag[row]) {
        *(float4*)(orow + lane * 4) = *(const float4*)&sig[lane * 4];
    } else {
        const unsigned* mrow = spk_buf + (size_t)row * 32;
        unsigned w = mrow[lane];
        float acc0 = b_out[lane * 4 + 0], acc1 = b_out[lane * 4 + 1];
        float acc2 = b_out[lane * 4 + 2], acc3 = b_out[lane * 4 + 3];
        for (int ww = 0; ww < 32; ww++) {
            unsigned m = __shfl_sync(0xffffffffu, w, ww);
            while (m) {
                int j = ww * 32 + __ffs((int)m) - 1;
                m &= m - 1;
                const float* wo = W_out + j;
                acc0 += wo[(size_t)(lane * 4 + 0) * H_];
                acc1 += wo[(size_t)(lane * 4 + 1) * H_];
                acc2 += wo[(size_t)(lane * 4 + 2) * H_];
                acc3 += wo[(size_t)(lane * 4 + 3) * H_];
            }
        }
        orow[lane * 4 + 0] = sigmoidf_(acc0);
        orow[lane * 4 + 1] = sigmoidf_(acc1);
        orow[lane * 4 + 2] = sigmoidf_(acc2);
        orow[lane * 4 + 3] = sigmoidf_(acc3);
    }
}

// ---------------------------------------------------------------------------
extern "C" void kernel_launch(void* const* d_in, const int* in_sizes, int n_in,
                              void* d_out, int out_size) {
    const float* x     = (const float*)d_in[0];
    const float* W_in  = (const float*)d_in[1];
    const float* b_in  = (const float*)d_in[2];
    const float* W_rec = (const float*)d_in[3];
    const float* b_rec = (const float*)d_in[4];
    const float* tau_m = (const float*)d_in[5];
    const float* tau_n = (const float*)d_in[6];
    const float* W_out = (const float*)d_in[7];
    const float* b_out = (const float*)d_in[8];
    float* out = (float*)d_out;

    static int attr_done = 0;
    if (!attr_done) {
        cudaFuncSetAttribute(ff_gemm_kernel, cudaFuncAttributeMaxDynamicSharedMemorySize, SMEM_BYTES);
        attr_done = 1;
    }

    prep_kernel<<<256, 1024>>>(W_in, b_in, b_rec, tau_m, tau_n);
    ff_gemm_kernel<<<1024, 512, SMEM_BYTES>>>(x);
    scan_kernel<<<128, 512>>>(tau_m, tau_n, W_rec);
    out_kernel<<<B_ * S_ / 8, 256>>>(W_out, b_out, out);
}

// round 9
// speedup vs baseline: 1.0504x; 1.0504x over previous
#include <cuda_runtime.h>
#include <cuda_bf16.h>
#include <math.h>
#include <stdint.h>

#define B_ 64
#define S_ 512
#define I_ 256
#define H_ 1024
#define O_ 128
#define BK 32

// ---------------- static device scratch (no dynamic allocation) ------------
__device__ __nv_bfloat16 g_buf[((size_t)B_ * S_ + 32) * H_]; // g2=(1-a)(1-b)(ff+bias), bf16 (+32 rows prefetch pad)
__device__ __nv_bfloat16 xbf[(size_t)B_ * S_ * I_];          // x in bf16
__device__ __nv_bfloat16 wbf[(size_t)H_ * I_];               // W_in in bf16
__device__ unsigned      spk_buf[(size_t)B_ * S_ * (H_ / 32)];
__device__ float         s1_buf[H_];                          // (1-alpha)(1-beta)
__device__ float         s2_buf[H_];                          // b_in + b_rec
__device__ unsigned      chunk_sync[B_ * 8];                  // per (batch,chunk) cross-CTA combine
__device__ unsigned      step_sync[B_ * S_];                  // per (batch,step) combine (replay path)

__device__ __forceinline__ float sigmoidf_(float x) { return 1.f / (1.f + expf(-x)); }

__device__ __forceinline__ uint32_t smem_u32(const void* p) {
    uint32_t a;
    asm("{ .reg .u64 t; cvta.to.shared.u64 t, %1; cvt.u32.u64 %0, t; }" : "=r"(a) : "l"(p));
    return a;
}
__device__ __forceinline__ void cp_async16(uint32_t dst, const void* src) {
    asm volatile("cp.async.cg.shared.global [%0], [%1], 16;" :: "r"(dst), "l"(src) : "memory");
}
__device__ __forceinline__ void cp_commit() {
    asm volatile("cp.async.commit_group;" ::: "memory");
}
__device__ __forceinline__ void ldmatrix_x4(unsigned& r0, unsigned& r1, unsigned& r2, unsigned& r3,
                                            uint32_t addr) {
    asm volatile("ldmatrix.sync.aligned.m8n8.x4.shared.b16 {%0,%1,%2,%3}, [%4];"
                 : "=r"(r0), "=r"(r1), "=r"(r2), "=r"(r3) : "r"(addr));
}

// ---------------------------------------------------------------------------
// Phase 0: x -> bf16 (blocks 0..2047), W_in -> bf16 + constants + zero flags
// (blocks 2048..2303). One kernel, one launch.
// ---------------------------------------------------------------------------
__global__ void cvt_kernel(const float* __restrict__ x, const float* __restrict__ W_in,
                           const float* __restrict__ b_in, const float* __restrict__ b_rec,
                           const float* __restrict__ tau_m, const float* __restrict__ tau_n) {
    int bid = blockIdx.x;
    if (bid < 2048) {
        size_t i = (size_t)bid * 1024 + threadIdx.x;
        float4 v = ((const float4*)x)[i];
        __nv_bfloat162 a = __floats2bfloat162_rn(v.x, v.y);
        __nv_bfloat162 b = __floats2bfloat162_rn(v.z, v.w);
        ((uint2*)xbf)[i] = make_uint2(*(unsigned*)&a, *(unsigned*)&b);
    } else {
        int idx = (bid - 2048) * 1024 + threadIdx.x;     // 0..262143
        wbf[idx] = __float2bfloat16(W_in[idx]);
        if (idx < B_ * S_) step_sync[idx] = 0;
        if (idx < B_ * 8)  chunk_sync[idx] = 0;
        if (bid == 2048) {
            int h = threadIdx.x;
            float a1 = 1.f - sigmoidf_(tau_m[h]);
            float b1 = 1.f - sigmoidf_(tau_n[h]);
            s1_buf[h] = a1 * b1;
            s2_buf[h] = b_in[h] + b_rec[h];
        }
    }
}

// ---------------------------------------------------------------------------
// Phase 1: HMMA GEMM with ldmatrix fragments + persistent B tile.
// g[m][n] = s1[n]*(X[m,:]·W[n,:] + s2[n]), bf16 out.
// Grid = 8 N-tiles x 64 M-groups = 512 CTAs, 256 thr (8 warps, warp 64x32).
// Each CTA: B tile (128x256 bf16, row stride 528B, conflict-free) loaded ONCE;
// 4 M-tiles of 128 streamed through a 3-stage cp.async A pipeline (row 80B).
// ---------------------------------------------------------------------------
#define ASTG   10240                     // 128 rows * 80B
#define SM_B   (3 * ASTG)                // 30720
#define BROW   528
#define SM_S12 (SM_B + 128 * BROW)       // 98304
#define SMEM_BYTES (SM_S12 + 128 * 8)    // 99328

__global__ __launch_bounds__(256, 1)
void ff_gemm_kernel() {
    extern __shared__ char smem[];
    uint32_t sa  = smem_u32(smem);
    uint32_t sbm = sa + SM_B;
    float2* s12 = (float2*)(smem + SM_S12);

    int tid = threadIdx.x, lane = tid & 31, warp = tid >> 5;
    int nt = blockIdx.x & 7, mg = blockIdx.x >> 3;
    int n0 = nt * 128;

    if (tid < 128) s12[tid] = make_float2(s1_buf[n0 + tid], s2_buf[n0 + tid]);

    // B preload: 128 rows x 512B = 4096 16B chunks, 16 per thread
    const __nv_bfloat16* Bb = wbf + (size_t)n0 * I_;
#pragma unroll
    for (int i = 0; i < 16; i++) {
        int idx = tid + i * 256; int row = idx >> 5; int c = idx & 31;
        cp_async16(sbm + row * BROW + c * 16, Bb + (size_t)row * I_ + c * 8);
    }
    cp_commit();

    const __nv_bfloat16* Am = xbf + (size_t)mg * 4 * 128 * I_;
    int ar0 = (tid * 2) >> 2, ac0 = (tid * 2) & 3;
    int ar1 = (tid * 2 + 1) >> 2, ac1 = (tid * 2 + 1) & 3;

#define ISSUE(j) do { int st = (j) % 3;                                          \
        const __nv_bfloat16* Ab = Am + (size_t)((j) >> 3) * 128 * I_ + ((j) & 7) * BK; \
        cp_async16(sa + st * ASTG + ar0 * 80 + ac0 * 16, Ab + (size_t)ar0 * I_ + ac0 * 8); \
        cp_async16(sa + st * ASTG + ar1 * 80 + ac1 * 16, Ab + (size_t)ar1 * I_ + ac1 * 8); \
        cp_commit(); } while (0)

    ISSUE(0);
    ISSUE(1);

    int wm = (warp >> 2) * 64;   // 0 or 64
    int wn = (warp & 3) * 32;    // 0..96
    int fr = lane >> 2, fc = (lane & 3) * 2;
    // ldmatrix lane address components
    int a_row = (lane & 7) + ((lane >> 3) & 1) * 8;
    int a_c16 = (lane >> 4) * 16;
    int b_row = wn + ((lane >> 4) & 1) * 8 + (lane & 7);
    int b_c16 = ((lane >> 3) & 1) * 16;

    float acc[4][4][4];
#pragma unroll
    for (int i = 0; i < 4; i++)
#pragma unroll
        for (int j = 0; j < 4; j++)
#pragma unroll
            for (int r = 0; r < 4; r++) acc[i][j][r] = 0.f;

    for (int it = 0; it < 32; it++) {
        if (it < 31) asm volatile("cp.async.wait_group 1;" ::: "memory");
        else         asm volatile("cp.async.wait_group 0;" ::: "memory");
        __syncthreads();
        if (it + 2 < 32) ISSUE(it + 2);

        uint32_t abuf = sa + (it % 3) * ASTG;
        int ktc = (it & 7) * 64;   // byte offset of this k-tile within a B row
#pragma unroll
        for (int ks = 0; ks < 2; ks++) {
            unsigned afr[4][4], bfr[4][2];
#pragma unroll
            for (int mi = 0; mi < 4; mi++) {
                uint32_t addr = abuf + (wm + mi * 16 + a_row) * 80 + ks * 32 + a_c16;
                ldmatrix_x4(afr[mi][0], afr[mi][1], afr[mi][2], afr[mi][3], addr);
            }
#pragma unroll
            for (int p = 0; p < 2; p++) {
                uint32_t addr = sbm + (b_row + p * 16) * BROW + ktc + ks * 32 + b_c16;
                ldmatrix_x4(bfr[2 * p][0], bfr[2 * p][1], bfr[2 * p + 1][0], bfr[2 * p + 1][1], addr);
            }
#pragma unroll
            for (int mi = 0; mi < 4; mi++)
#pragma unroll
                for (int ni = 0; ni < 4; ni++) {
                    asm volatile(
                        "mma.sync.aligned.m16n8k16.row.col.f32.bf16.bf16.f32 "
                        "{%0,%1,%2,%3}, {%4,%5,%6,%7}, {%8,%9}, {%0,%1,%2,%3};"
                        : "+f"(acc[mi][ni][0]), "+f"(acc[mi][ni][1]),
                          "+f"(acc[mi][ni][2]), "+f"(acc[mi][ni][3])
                        : "r"(afr[mi][0]), "r"(afr[mi][1]), "r"(afr[mi][2]), "r"(afr[mi][3]),
                          "r"(bfr[ni][0]), "r"(bfr[ni][1]));
                }
        }

        if ((it & 7) == 7) {
            // epilogue for M-tile (it>>3): g = s1*(c + s2), bf16
            int m0 = (mg * 4 + (it >> 3)) * 128;
#pragma unroll
            for (int mi = 0; mi < 4; mi++) {
#pragma unroll
                for (int ni = 0; ni < 4; ni++) {
                    int nloc = wn + ni * 8 + fc;
                    int n = n0 + nloc;
                    float2 pa = s12[nloc], pb = s12[nloc + 1];
                    int ma = m0 + wm + mi * 16 + fr;
                    *(__nv_bfloat162*)&g_buf[(size_t)ma * H_ + n] =
                        __floats2bfloat162_rn(pa.x * (acc[mi][ni][0] + pa.y),
                                              pb.x * (acc[mi][ni][1] + pb.y));
                    *(__nv_bfloat162*)&g_buf[(size_t)(ma + 8) * H_ + n] =
                        __floats2bfloat162_rn(pa.x * (acc[mi][ni][2] + pa.y),
                                              pb.x * (acc[mi][ni][3] + pb.y));
                    acc[mi][ni][0] = acc[mi][ni][1] = acc[mi][ni][2] = acc[mi][ni][3] = 0.f;
                }
            }
        }
    }
#undef ISSUE
}

// ---------------------------------------------------------------------------
// Phase 2: speculative chunked scan + fused output. 4 CTAs per batch
// (256 neurons each, all 256 CTAs co-resident -> safe L2-flag spin).
// D = beta*D + g2 (+ s1c*rec); mem = alpha*mem + D; spike iff mem>1.
// Fast path per 64-step chunk: ONE block barrier + ONE cross-CTA combine,
// then sub==0 writes out rows = sigmoid(b_out) directly.
// Cold path: exact per-step replay (ballot + sparse W_rec gather + per-step
// cross-CTA sync + sparse W_out output).
// ---------------------------------------------------------------------------
__global__ __launch_bounds__(256, 1)
void scan_kernel(const float* __restrict__ tau_m, const float* __restrict__ tau_n,
                 const float* __restrict__ W_rec, const float* __restrict__ W_out,
                 const float* __restrict__ b_out, float* __restrict__ out) {
    __shared__ int s_any;
    __shared__ float4 sig4[32];
    int bc = blockIdx.x;          // 0..255
    int b = bc >> 2, sub = bc & 3;
    int tid = threadIdx.x;
    int h = sub * 256 + tid;

    float alpha = sigmoidf_(tau_m[h]);
    float beta  = sigmoidf_(tau_n[h]);
    float s1c = (1.f - alpha) * (1.f - beta);
    const __nv_bfloat16* gp = g_buf + (size_t)b * S_ * H_ + h;
    unsigned* spkrow = spk_buf + (size_t)b * S_ * 32;
    const float* wr = W_rec + (size_t)h * H_;
    float* outb = out + (size_t)b * S_ * O_;

    if (tid < 128) ((float*)sig4)[tid] = sigmoidf_(b_out[tid]);
    __syncthreads();

    float mem = 0.f, D = 0.f;
    __nv_bfloat16 ring[32];
#pragma unroll
    for (int i = 0; i < 32; i++) ring[i] = gp[(size_t)i * H_];
    const __nv_bfloat16* pf = gp + (size_t)32 * H_;   // g_buf has +32 rows pad

    int carry = 0;
    for (int chunk = 0; chunk < 8; chunk++) {
        int base = chunk * 64;
        float mem0 = mem, D0 = D, maxm = 0.f;
        for (int u = 0; u < 2; u++) {
#pragma unroll
            for (int v = 0; v < 32; v++) {
                float gv = __bfloat162float(ring[v]);
                ring[v] = *pf; pf += H_;
                D = fmaf(beta, D, gv);
                mem = fmaf(alpha, mem, D);
                maxm = fmaxf(maxm, mem);
            }
        }
        int lany = __syncthreads_or(maxm > 1.f);
        if (tid == 0) {
            __threadfence();
            atomicAdd(&chunk_sync[b * 8 + chunk], 0x10000u | (unsigned)lany);
            unsigned v;
            do { v = *((volatile unsigned*)&chunk_sync[b * 8 + chunk]); } while ((v >> 16) < 4u);
            __threadfence();
            s_any = (int)(v & 0xFFFFu);
        }
        __syncthreads();
        int any = s_any;
        __syncthreads();

        if (!(any | carry)) {
            if (sub == 0) {
                float4* o4 = (float4*)(outb + (size_t)base * O_);
#pragma unroll
                for (int i = 0; i < 8; i++) {
                    int idx = tid + i * 256;           // 2048 float4 = 64 rows x 32
                    o4[idx] = sig4[idx & 31];
                }
            }
            carry = 0;
        } else {
            // exact replay of this chunk (cold path)
            mem = mem0; D = D0;
            int prev = carry;
            for (int tt = 0; tt < 64; tt++) {
                int t = base + tt;
                float rec = 0.f;
                if (prev) {
                    const unsigned* mrow = spkrow + (size_t)(t - 1) * 32;
                    for (int w2 = 0; w2 < 32; w2++) {
                        unsigned msk = mrow[w2];
                        while (msk) {
                            int j = __ffs((int)msk) - 1;
                            rec += wr[w2 * 32 + j];
                            msk &= msk - 1;
                        }
                    }
                }
                float gv = __bfloat162float(gp[(size_t)t * H_]);
                D = fmaf(beta, D, fmaf(s1c, rec, gv));
                mem = fmaf(alpha, mem, D);
                int spike = mem > 1.f;
                if (spike) mem = 0.f;
                unsigned bal = __ballot_sync(0xffffffffu, spike);
                if ((tid & 31) == 0) spkrow[(size_t)t * 32 + sub * 8 + (tid >> 5)] = bal;
                int lor = __syncthreads_or(spike);
                if (tid == 0) {
                    __threadfence();
                    atomicAdd(&step_sync[b * S_ + t], 0x10000u | (unsigned)lor);
                    unsigned v;
                    do { v = *((volatile unsigned*)&step_sync[b * S_ + t]); } while ((v >> 16) < 4u);
                    __threadfence();
                    s_any = (int)(v & 0xFFFFu);
                }
                __syncthreads();
                prev = s_any ? 1 : 0;
                __syncthreads();
                if (sub == 0 && tid < 128) {
                    // out[b,t,tid] = sigmoid(b_out + sum_{j spiking} W_out[tid][j])
                    float acc = b_out[tid];
                    const unsigned* mrow = spkrow + (size_t)t * 32;
                    for (int w2 = 0; w2 < 32; w2++) {
                        unsigned msk = mrow[w2];
                        while (msk) {
                            int j = __ffs((int)msk) - 1;
                            acc += W_out[(size_t)tid * H_ + w2 * 32 + j];
                            msk &= msk - 1;
                        }
                    }
                    outb[(size_t)t * O_ + tid] = sigmoidf_(acc);
                }
            }
            carry = prev;
        }
    }
}

// ---------------------------------------------------------------------------
extern "C" void kernel_launch(void* const* d_in, const int* in_sizes, int n_in,
                              void* d_out, int out_size) {
    const float* x     = (const float*)d_in[0];
    const float* W_in  = (const float*)d_in[1];
    const float* b_in  = (const float*)d_in[2];
    const float* W_rec = (const float*)d_in[3];
    const float* b_rec = (const float*)d_in[4];
    const float* tau_m = (const float*)d_in[5];
    const float* tau_n = (const float*)d_in[6];
    const float* W_out = (const float*)d_in[7];
    const float* b_out = (const float*)d_in[8];
    float* out = (float*)d_out;

    static int attr_done = 0;
    if (!attr_done) {
        cudaFuncSetAttribute(ff_gemm_kernel, cudaFuncAttributeMaxDynamicSharedMemorySize, SMEM_BYTES);
        attr_done = 1;
    }

    cvt_kernel<<<2304, 1024>>>(x, W_in, b_in, b_rec, tau_m, tau_n);
    ff_gemm_kernel<<<512, 256, SMEM_BYTES>>>();
    scan_kernel<<<256, 256>>>(tau_m, tau_n, W_rec, W_out, b_out, out);
}